// round 9
// baseline (speedup 1.0000x reference)
#include <cuda_runtime.h>
#include <cuda_bf16.h>
#include <cstdint>

// Problem constants
#define Bdim 8
#define Nseq 4096
#define Cdim 768
#define Hh   12
#define Dd   64
#define Mrows (Bdim * Nseq)      // 32768
#define ThreeC (3 * Cdim)        // 2304
#define BH (Bdim * Hh)           // 96
#define NSPLIT 16
#define KSPLIT 2304              // K' = 3*768 (hi/hi/lo folded split)

// Main GEMM tiling (R5 config: best known)
#define BM 128
#define BN 256
#define BKK 32
#define KT2 (KSPLIT / BKK)       // 72
#define ROWB 80
#define ATILE (BM * ROWB)
#define BTILE (BN * ROWB)
#define STG (ATILE + BTILE)      // 30720
#define NSTAGE 4
#define GEMM_SMEM (NSTAGE * STG) // 122880

// ctx / attn smem row stride (bf16 elems): 64 data + 8 pad
#define CROW 72
#define CTX_SMEM  (4*128*CROW*2 + 128*65*4 + 64*4)   // 107264
#define ATTN_SMEM (2*128*CROW*2 + 2*64*CROW*2)       // 55296

// ---------------------------------------------------------------------------
// Scratch (device globals -- no allocation allowed)
// ---------------------------------------------------------------------------
__device__ __nv_bfloat16  g_xhi[(size_t)Mrows * Cdim];
__device__ __nv_bfloat16  g_xlo[(size_t)Mrows * Cdim];
__device__ __nv_bfloat16  g_qh[(size_t)Mrows * Cdim];
__device__ __nv_bfloat16  g_ql[(size_t)Mrows * Cdim];
__device__ __nv_bfloat16  g_kh[(size_t)Mrows * Cdim];
__device__ __nv_bfloat16  g_kl[(size_t)Mrows * Cdim];
__device__ __nv_bfloat16  g_vh[(size_t)Mrows * Cdim];
__device__ __nv_bfloat16  g_vl[(size_t)Mrows * Cdim];
__device__ __nv_bfloat16  g_ahi[(size_t)Mrows * Cdim];
__device__ __nv_bfloat16  g_alo[(size_t)Mrows * Cdim];
__device__ __nv_bfloat16  g_bqkv[(size_t)ThreeC * KSPLIT];
__device__ __nv_bfloat16  g_bproj[(size_t)Cdim * KSPLIT];
__device__ float g_psum[NSPLIT * BH * Dd];
__device__ float g_ctxp[(size_t)NSPLIT * BH * Dd * Dd];
__device__ __nv_bfloat16 g_cth[(size_t)BH * Dd * Dd];   // ctx^T hi: [bh][e][d]
__device__ __nv_bfloat16 g_ctl[(size_t)BH * Dd * Dd];   // ctx^T lo

// ---------------------------------------------------------------------------
// PTX helpers
// ---------------------------------------------------------------------------
__device__ __forceinline__ uint32_t smem_u32_of(const void* p) {
    uint32_t a;
    asm("{ .reg .u64 t; cvta.to.shared.u64 t, %1; cvt.u32.u64 %0, t; }"
        : "=r"(a) : "l"(p));
    return a;
}

__device__ __forceinline__ void cp_async16(uint32_t dst, const void* src) {
    asm volatile("cp.async.cg.shared.global [%0], [%1], 16;\n"
                 :: "r"(dst), "l"(src) : "memory");
}
#define CP_COMMIT() asm volatile("cp.async.commit_group;" ::: "memory")
#define CP_WAIT2()  asm volatile("cp.async.wait_group 2;" ::: "memory")
#define CP_WAIT1()  asm volatile("cp.async.wait_group 1;" ::: "memory")
#define CP_WAIT0()  asm volatile("cp.async.wait_group 0;" ::: "memory")

__device__ __forceinline__ void ldmatrix_x4(uint32_t* r, uint32_t addr) {
    asm volatile(
        "ldmatrix.sync.aligned.m8n8.x4.shared.b16 {%0,%1,%2,%3}, [%4];"
        : "=r"(r[0]), "=r"(r[1]), "=r"(r[2]), "=r"(r[3]) : "r"(addr));
}

__device__ __forceinline__ void ldmatrix_x4_t(uint32_t* r, uint32_t addr) {
    asm volatile(
        "ldmatrix.sync.aligned.m8n8.x4.trans.shared.b16 {%0,%1,%2,%3}, [%4];"
        : "=r"(r[0]), "=r"(r[1]), "=r"(r[2]), "=r"(r[3]) : "r"(addr));
}

__device__ __forceinline__ void mma16816(float* d, const uint32_t* a,
                                         const uint32_t* b) {
    asm volatile(
        "mma.sync.aligned.m16n8k16.row.col.f32.bf16.bf16.f32 "
        "{%0,%1,%2,%3}, {%4,%5,%6,%7}, {%8,%9}, {%0,%1,%2,%3};"
        : "+f"(d[0]), "+f"(d[1]), "+f"(d[2]), "+f"(d[3])
        : "r"(a[0]), "r"(a[1]), "r"(a[2]), "r"(a[3]), "r"(b[0]), "r"(b[1]));
}

__device__ __forceinline__ void split2(float v, __nv_bfloat16& h, __nv_bfloat16& l) {
    h = __float2bfloat16(v);
    l = __float2bfloat16(v - __bfloat162float(h));
}

// ---------------------------------------------------------------------------
// Main GEMM (R5 config): BM=128 BN=256 BK=32, 512 threads, warp 4m x 4n,
// 4-stage cp.async pipeline. Two epilogue variants via template.
// ---------------------------------------------------------------------------
__device__ __forceinline__ void gemm_load_stage(
    const __nv_bfloat16* __restrict__ Ahi, const __nv_bfloat16* __restrict__ Alo,
    const __nv_bfloat16* __restrict__ Bt,
    size_t m0, size_t n0, int kt, int stage, uint32_t sb, int tid)
{
    int blk = kt / 24;
    const __nv_bfloat16* asrc = (blk < 2) ? Ahi : Alo;
    int acol = (kt - blk * 24) * BKK;
    int bcol = kt * BKK;
    uint32_t as = sb + stage * STG;
    uint32_t bs = as + ATILE;
    int lr = tid >> 2;
    int lc = tid & 3;

    cp_async16(as + lr * ROWB + lc * 16,
               asrc + (m0 + lr) * Cdim + acol + lc * 8);
    cp_async16(bs + lr * ROWB + lc * 16,
               Bt + (n0 + lr) * (size_t)KSPLIT + bcol + lc * 8);
    cp_async16(bs + (lr + 128) * ROWB + lc * 16,
               Bt + (n0 + lr + 128) * (size_t)KSPLIT + bcol + lc * 8);
    CP_COMMIT();
}

template <bool SPLIT_OUT>
__global__ __launch_bounds__(512, 1) void gemm_hmma_kernel(
    const __nv_bfloat16* __restrict__ Ahi,
    const __nv_bfloat16* __restrict__ Alo,
    const __nv_bfloat16* __restrict__ Bt,
    float* __restrict__ Cm, int ldc,
    const float* __restrict__ bias)
{
    extern __shared__ char smem[];
    uint32_t sb = smem_u32_of(smem);
    int tid = threadIdx.x;
    int lane = tid & 31, wid = tid >> 5;
    int wm = wid >> 2, wn = wid & 3;

    size_t m0 = (size_t)blockIdx.y * BM;
    size_t n0 = (size_t)blockIdx.x * BN;

    uint32_t a_off = (uint32_t)(wm * 32 + (lane & 15)) * ROWB + ((lane >> 4) << 4);
    uint32_t b_off = ATILE +
        (uint32_t)(wn * 64 + (lane & 7) + ((lane >> 4) << 3)) * ROWB +
        ((lane & 8) << 1);

    float acc[2][8][4];
    #pragma unroll
    for (int mf = 0; mf < 2; mf++)
        #pragma unroll
        for (int nf = 0; nf < 8; nf++)
            #pragma unroll
            for (int c = 0; c < 4; c++) acc[mf][nf][c] = 0.f;

    gemm_load_stage(Ahi, Alo, Bt, m0, n0, 0, 0, sb, tid);
    gemm_load_stage(Ahi, Alo, Bt, m0, n0, 1, 1, sb, tid);
    gemm_load_stage(Ahi, Alo, Bt, m0, n0, 2, 2, sb, tid);

    for (int kt = 0; kt < KT2; kt++) {
        int rem = KT2 - 1 - kt;
        if (rem >= 2) CP_WAIT2();
        else if (rem == 1) CP_WAIT1();
        else CP_WAIT0();
        __syncthreads();
        if (kt + 3 < KT2)
            gemm_load_stage(Ahi, Alo, Bt, m0, n0, kt + 3, (kt + 3) & 3, sb, tid);

        uint32_t stg = sb + (kt & 3) * STG;
        #pragma unroll
        for (int ks = 0; ks < 2; ks++) {
            uint32_t aF[2][4];
            uint32_t bF[4][4];
            #pragma unroll
            for (int mf = 0; mf < 2; mf++)
                ldmatrix_x4(aF[mf], stg + a_off + mf * (16 * ROWB) + ks * 32);
            #pragma unroll
            for (int nf2 = 0; nf2 < 4; nf2++)
                ldmatrix_x4(bF[nf2], stg + b_off + nf2 * (16 * ROWB) + ks * 32);
            #pragma unroll
            for (int mf = 0; mf < 2; mf++)
                #pragma unroll
                for (int nf = 0; nf < 8; nf++)
                    mma16816(acc[mf][nf], aF[mf], &bF[nf >> 1][(nf & 1) * 2]);
        }
    }

    if (!SPLIT_OUT) {
        #pragma unroll
        for (int mf = 0; mf < 2; mf++) {
            size_t row = m0 + wm * 32 + mf * 16 + (lane >> 2);
            #pragma unroll
            for (int nf = 0; nf < 8; nf++) {
                int col = (int)n0 + wn * 64 + nf * 8 + (lane & 3) * 2;
                float b0 = bias ? bias[col] : 0.f;
                float b1 = bias ? bias[col + 1] : 0.f;
                float2 v0; v0.x = acc[mf][nf][0] + b0; v0.y = acc[mf][nf][1] + b1;
                float2 v1; v1.x = acc[mf][nf][2] + b0; v1.y = acc[mf][nf][3] + b1;
                *reinterpret_cast<float2*>(&Cm[row * (size_t)ldc + col]) = v0;
                *reinterpret_cast<float2*>(&Cm[(row + 8) * (size_t)ldc + col]) = v1;
            }
        }
    } else {
        // qkv epilogue: route to (qh,ql)/(kh,kl)/(vh,vl) by column block, bf16 split
        int blk = (int)(n0 / Cdim);
        __nv_bfloat16 *dh, *dl;
        if (blk == 0)      { dh = g_qh; dl = g_ql; }
        else if (blk == 1) { dh = g_kh; dl = g_kl; }
        else               { dh = g_vh; dl = g_vl; }
        int c0 = (int)n0 - blk * Cdim;
        #pragma unroll
        for (int mf = 0; mf < 2; mf++) {
            size_t row = m0 + wm * 32 + mf * 16 + (lane >> 2);
            #pragma unroll
            for (int nf = 0; nf < 8; nf++) {
                int c = c0 + wn * 64 + nf * 8 + (lane & 3) * 2;
                #pragma unroll
                for (int half = 0; half < 2; half++) {
                    size_t r = row + half * 8;
                    __nv_bfloat16 h0, l0, h1, l1;
                    split2(acc[mf][nf][half * 2 + 0], h0, l0);
                    split2(acc[mf][nf][half * 2 + 1], h1, l1);
                    __nv_bfloat162 ph; ph.x = h0; ph.y = h1;
                    __nv_bfloat162 pl; pl.x = l0; pl.y = l1;
                    *reinterpret_cast<__nv_bfloat162*>(&dh[r * Cdim + c]) = ph;
                    *reinterpret_cast<__nv_bfloat162*>(&dl[r * Cdim + c]) = pl;
                }
            }
        }
    }
}

// ---------------------------------------------------------------------------
// Split fp32 -> (hi, lo) bf16 (x input)
// ---------------------------------------------------------------------------
__global__ __launch_bounds__(256) void split_kernel(
    const float* __restrict__ in, __nv_bfloat16* __restrict__ hi,
    __nv_bfloat16* __restrict__ lo, int n4)
{
    int i = blockIdx.x * 256 + threadIdx.x;
    if (i >= n4) return;
    float4 v = reinterpret_cast<const float4*>(in)[i];
    __nv_bfloat16 h0, h1, h2, h3, l0, l1, l2, l3;
    split2(v.x, h0, l0); split2(v.y, h1, l1);
    split2(v.z, h2, l2); split2(v.w, h3, l3);
    __nv_bfloat162* hp = reinterpret_cast<__nv_bfloat162*>(hi) + i * 2;
    __nv_bfloat162* lp = reinterpret_cast<__nv_bfloat162*>(lo) + i * 2;
    __nv_bfloat162 a; a.x = h0; a.y = h1;
    __nv_bfloat162 b; b.x = h2; b.y = h3;
    __nv_bfloat162 c; c.x = l0; c.y = l1;
    __nv_bfloat162 d; d.x = l2; d.y = l3;
    hp[0] = a; hp[1] = b; lp[0] = c; lp[1] = d;
}

// ---------------------------------------------------------------------------
// Build transposed split weight: W [768 x Nn] fp32 -> Bt [Nn x 2304] bf16
// ---------------------------------------------------------------------------
__global__ __launch_bounds__(256) void build_bt_kernel(
    const float* __restrict__ W, __nv_bfloat16* __restrict__ Bt, int Nn)
{
    __shared__ float t[32][33];
    int n0 = blockIdx.x * 32, k0 = blockIdx.y * 32;
    int tx = threadIdx.x, ty = threadIdx.y;
    #pragma unroll
    for (int j = 0; j < 32; j += 8)
        t[ty + j][tx] = W[(size_t)(k0 + ty + j) * Nn + n0 + tx];
    __syncthreads();
    #pragma unroll
    for (int j = 0; j < 32; j += 8) {
        int n = n0 + ty + j, k = k0 + tx;
        float v = t[tx][ty + j];
        __nv_bfloat16 h, l;
        split2(v, h, l);
        size_t base = (size_t)n * KSPLIT;
        Bt[base + k] = h;
        Bt[base + 768 + k] = l;
        Bt[base + 1536 + k] = h;
    }
}

// ---------------------------------------------------------------------------
// ctx kernel (HMMA): per (bh, split) computes
//   ctxp[sp][bh][d][e] = sum_n exp(k[n,d]) * v[n,e],  psum[sp][bh][d]
// E = exp(k) split hi/lo in-kernel; V pre-split. 3-term MMA with trans frags.
// 128 threads, warps 2(d) x 2(e), warp tile 32x32.
// ---------------------------------------------------------------------------
__global__ __launch_bounds__(128, 1) void ctx_hmma_kernel()
{
    extern __shared__ char cs[];
    __nv_bfloat16* e_hi = reinterpret_cast<__nv_bfloat16*>(cs);
    __nv_bfloat16* e_lo = e_hi + 128 * CROW;
    __nv_bfloat16* v_hi = e_lo + 128 * CROW;
    __nv_bfloat16* v_lo = v_hi + 128 * CROW;
    float* e_f  = reinterpret_cast<float*>(v_lo + 128 * CROW);  // [128][65]
    float* psum = e_f + 128 * 65;

    uint32_t e_hi_s = smem_u32_of(e_hi);
    uint32_t e_lo_s = smem_u32_of(e_lo);
    uint32_t v_hi_s = smem_u32_of(v_hi);
    uint32_t v_lo_s = smem_u32_of(v_lo);

    int bh = blockIdx.x, sp = blockIdx.y;
    int b = bh / Hh, h = bh - b * Hh;
    int tid = threadIdx.x, lane = tid & 31, wid = tid >> 5;
    int wm = wid >> 1, wn = wid & 1;

    if (tid < 64) psum[tid] = 0.f;

    float acc[2][4][4];
    #pragma unroll
    for (int mf = 0; mf < 2; mf++)
        #pragma unroll
        for (int nf = 0; nf < 4; nf++)
            #pragma unroll
            for (int c = 0; c < 4; c++) acc[mf][nf][c] = 0.f;

    // Per-thread trans-ldmatrix offsets (byte): row stride 144
    uint32_t a_tr = ((lane & 7) + ((lane >> 4) & 1) * 8) * 144 +
                    (wm * 32 + ((lane >> 3) & 1) * 8) * 2;
    uint32_t b_tr = ((lane & 7) + ((lane >> 3) & 1) * 8) * 144 +
                    (wn * 32 + ((lane >> 4) & 1) * 8) * 2;

    size_t row0 = (size_t)b * Nseq + (size_t)sp * (Nseq / NSPLIT);

    for (int ch = 0; ch < 2; ch++) {
        int r = tid;
        size_t grow = row0 + ch * 128 + r;
        // v hi/lo rows via cp.async (already bf16 split)
        {
            const char* vhs = reinterpret_cast<const char*>(g_vh + grow * Cdim + h * Dd);
            const char* vls = reinterpret_cast<const char*>(g_vl + grow * Cdim + h * Dd);
            uint32_t dh = v_hi_s + r * 144;
            uint32_t dl = v_lo_s + r * 144;
            #pragma unroll
            for (int i = 0; i < 8; i++) {
                cp_async16(dh + i * 16, vhs + i * 16);
                cp_async16(dl + i * 16, vls + i * 16);
            }
            CP_COMMIT();
        }
        // k -> e = exp(kh+kl), split, store; also fp32 copy for column sums
        {
            const float4* khp = reinterpret_cast<const float4*>(g_kh + grow * Cdim + h * Dd);
            const float4* klp = reinterpret_cast<const float4*>(g_kl + grow * Cdim + h * Dd);
            #pragma unroll
            for (int i = 0; i < 8; i++) {
                float4 a4 = khp[i], b4 = klp[i];
                const __nv_bfloat162* ah = reinterpret_cast<const __nv_bfloat162*>(&a4);
                const __nv_bfloat162* al = reinterpret_cast<const __nv_bfloat162*>(&b4);
                #pragma unroll
                for (int j = 0; j < 4; j++) {
                    int d = i * 8 + j * 2;
                    float k0 = __bfloat162float(ah[j].x) + __bfloat162float(al[j].x);
                    float k1 = __bfloat162float(ah[j].y) + __bfloat162float(al[j].y);
                    float e0 = __expf(k0), e1 = __expf(k1);
                    e_f[r * 65 + d] = e0;
                    e_f[r * 65 + d + 1] = e1;
                    __nv_bfloat16 h0, l0, h1, l1;
                    split2(e0, h0, l0); split2(e1, h1, l1);
                    __nv_bfloat162 ph; ph.x = h0; ph.y = h1;
                    __nv_bfloat162 pl; pl.x = l0; pl.y = l1;
                    *reinterpret_cast<__nv_bfloat162*>(&e_hi[r * CROW + d]) = ph;
                    *reinterpret_cast<__nv_bfloat162*>(&e_lo[r * CROW + d]) = pl;
                }
            }
        }
        CP_WAIT0();
        __syncthreads();

        // column sums of e (threads 0..63, one column each; exclusive writer)
        if (tid < 64) {
            float s = 0.f;
            #pragma unroll 8
            for (int rr = 0; rr < 128; rr++) s += e_f[rr * 65 + tid];
            psum[tid] += s;
        }

        // 3-term MMA: (Eh,Vh), (Eh,Vl), (El,Vh); K = 128 per chunk
        #pragma unroll
        for (int term = 0; term < 3; term++) {
            uint32_t As = (term == 2) ? e_lo_s : e_hi_s;
            uint32_t Bs = (term == 1) ? v_lo_s : v_hi_s;
            #pragma unroll
            for (int s8 = 0; s8 < 8; s8++) {
                uint32_t krow = s8 * (16 * 144);
                uint32_t aF[2][4], bF[2][4];
                #pragma unroll
                for (int mf = 0; mf < 2; mf++)
                    ldmatrix_x4_t(aF[mf], As + a_tr + krow + mf * 32);
                #pragma unroll
                for (int nb = 0; nb < 2; nb++)
                    ldmatrix_x4_t(bF[nb], Bs + b_tr + krow + nb * 32);
                #pragma unroll
                for (int mf = 0; mf < 2; mf++)
                    #pragma unroll
                    for (int nf = 0; nf < 4; nf++)
                        mma16816(acc[mf][nf], aF[mf], &bF[nf >> 1][(nf & 1) * 2]);
            }
        }
        __syncthreads();
    }

    // epilogue: fp32 partials
    float* outp = g_ctxp + ((size_t)sp * BH + bh) * (Dd * Dd);
    #pragma unroll
    for (int mf = 0; mf < 2; mf++) {
        int d0 = wm * 32 + mf * 16 + (lane >> 2);
        #pragma unroll
        for (int nf = 0; nf < 4; nf++) {
            int e0 = wn * 32 + nf * 8 + (lane & 3) * 2;
            outp[d0 * Dd + e0]           = acc[mf][nf][0];
            outp[d0 * Dd + e0 + 1]       = acc[mf][nf][1];
            outp[(d0 + 8) * Dd + e0]     = acc[mf][nf][2];
            outp[(d0 + 8) * Dd + e0 + 1] = acc[mf][nf][3];
        }
    }
    if (tid < 64)
        g_psum[((size_t)sp * BH + bh) * Dd + tid] = psum[tid];
}

// ---------------------------------------------------------------------------
// Reduce partials, normalize, write ctx^T as bf16 hi/lo ([bh][e][d])
// ---------------------------------------------------------------------------
__global__ __launch_bounds__(256) void ctx_reduce_kernel()
{
    int idx = blockIdx.x * 256 + threadIdx.x;
    const int total = BH * Dd * Dd;
    if (idx >= total) return;
    int bh = idx >> 12;
    int d = (idx >> 6) & 63;
    int e = idx & 63;
    float ksum = 0.f, s = 0.f;
    #pragma unroll
    for (int sp = 0; sp < NSPLIT; sp++) {
        ksum += g_psum[((size_t)sp * BH + bh) * Dd + d];
        s += g_ctxp[(size_t)sp * total + idx];
    }
    float v = s / ksum;
    __nv_bfloat16 h, l;
    split2(v, h, l);
    size_t o = ((size_t)bh << 12) + (e << 6) + d;
    g_cth[o] = h;
    g_ctl[o] = l;
}

// ---------------------------------------------------------------------------
// attn kernel (HMMA): out[n, h*64+e] = sum_d q[n,d] * ctxT[e,d], 3-term split.
// grid (BH, 32); 128 threads, warps 2(m) x 2(n), warp tile 64x32.
// Epilogue writes ahi/alo (A-side of GEMM2).
// ---------------------------------------------------------------------------
__global__ __launch_bounds__(128, 1) void attn_hmma_kernel()
{
    extern __shared__ char cs[];
    __nv_bfloat16* q_hi = reinterpret_cast<__nv_bfloat16*>(cs);
    __nv_bfloat16* q_lo = q_hi + 128 * CROW;
    __nv_bfloat16* c_hi = q_lo + 128 * CROW;
    __nv_bfloat16* c_lo = c_hi + 64 * CROW;

    uint32_t q_hi_s = smem_u32_of(q_hi);
    uint32_t q_lo_s = smem_u32_of(q_lo);
    uint32_t c_hi_s = smem_u32_of(c_hi);
    uint32_t c_lo_s = smem_u32_of(c_lo);

    int bh = blockIdx.x, nb = blockIdx.y;
    int b = bh / Hh, h = bh - b * Hh;
    int tid = threadIdx.x, lane = tid & 31, wid = tid >> 5;
    int wm = wid >> 1, wn = wid & 1;

    // loads
    {
        int r = tid;
        size_t grow = (size_t)b * Nseq + (size_t)nb * 128 + r;
        const char* qhs = reinterpret_cast<const char*>(g_qh + grow * Cdim + h * Dd);
        const char* qls = reinterpret_cast<const char*>(g_ql + grow * Cdim + h * Dd);
        #pragma unroll
        for (int i = 0; i < 8; i++) {
            cp_async16(q_hi_s + r * 144 + i * 16, qhs + i * 16);
            cp_async16(q_lo_s + r * 144 + i * 16, qls + i * 16);
        }
        if (tid < 64) {
            const char* chs = reinterpret_cast<const char*>(g_cth + ((size_t)bh << 12) + (tid << 6));
            const char* cls = reinterpret_cast<const char*>(g_ctl + ((size_t)bh << 12) + (tid << 6));
            #pragma unroll
            for (int i = 0; i < 8; i++) {
                cp_async16(c_hi_s + tid * 144 + i * 16, chs + i * 16);
                cp_async16(c_lo_s + tid * 144 + i * 16, cls + i * 16);
            }
        }
        CP_COMMIT();
    }
    CP_WAIT0();
    __syncthreads();

    float acc[4][4][4];
    #pragma unroll
    for (int mf = 0; mf < 4; mf++)
        #pragma unroll
        for (int nf = 0; nf < 4; nf++)
            #pragma unroll
            for (int c = 0; c < 4; c++) acc[mf][nf][c] = 0.f;

    uint32_t a_off = (uint32_t)(wm * 64 + (lane & 15)) * 144 + ((lane >> 4) << 4);
    uint32_t b_off = (uint32_t)(wn * 32 + (lane & 7) + ((lane >> 4) << 3)) * 144 +
                     ((lane & 8) << 1);

    #pragma unroll
    for (int term = 0; term < 3; term++) {
        uint32_t As = (term == 2) ? q_lo_s : q_hi_s;
        uint32_t Bs = (term == 1) ? c_lo_s : c_hi_s;
        #pragma unroll
        for (int s8 = 0; s8 < 4; s8++) {
            uint32_t kb = s8 * 32;  // k16 step in bytes
            uint32_t aF[4][4], bF[2][4];
            #pragma unroll
            for (int mf = 0; mf < 4; mf++)
                ldmatrix_x4(aF[mf], As + a_off + mf * (16 * 144) + kb);
            #pragma unroll
            for (int nbb = 0; nbb < 2; nbb++)
                ldmatrix_x4(bF[nbb], Bs + b_off + nbb * (16 * 144) + kb);
            #pragma unroll
            for (int mf = 0; mf < 4; mf++)
                #pragma unroll
                for (int nf = 0; nf < 4; nf++)
                    mma16816(acc[mf][nf], aF[mf], &bF[nf >> 1][(nf & 1) * 2]);
        }
    }

    // epilogue: split to ahi/alo
    #pragma unroll
    for (int mf = 0; mf < 4; mf++) {
        size_t row = (size_t)b * Nseq + (size_t)nb * 128 + wm * 64 + mf * 16 + (lane >> 2);
        #pragma unroll
        for (int nf = 0; nf < 4; nf++) {
            int c = h * Dd + wn * 32 + nf * 8 + (lane & 3) * 2;
            #pragma unroll
            for (int half = 0; half < 2; half++) {
                size_t r = row + half * 8;
                __nv_bfloat16 h0, l0, h1, l1;
                split2(acc[mf][nf][half * 2 + 0], h0, l0);
                split2(acc[mf][nf][half * 2 + 1], h1, l1);
                __nv_bfloat162 ph; ph.x = h0; ph.y = h1;
                __nv_bfloat162 pl; pl.x = l0; pl.y = l1;
                *reinterpret_cast<__nv_bfloat162*>(&g_ahi[r * Cdim + c]) = ph;
                *reinterpret_cast<__nv_bfloat162*>(&g_alo[r * Cdim + c]) = pl;
            }
        }
    }
}

// ---------------------------------------------------------------------------
extern "C" void kernel_launch(void* const* d_in, const int* in_sizes, int n_in,
                              void* d_out, int out_size)
{
    const float* x     = (const float*)d_in[0];
    const float* Wqkv  = (const float*)d_in[1];
    const float* Wproj = (const float*)d_in[2];
    const float* bproj = (const float*)d_in[3];
    float* out = (float*)d_out;

    __nv_bfloat16 *xhi, *xlo, *ahi, *alo, *bqkv, *bprojt;
    cudaGetSymbolAddress((void**)&xhi, g_xhi);
    cudaGetSymbolAddress((void**)&xlo, g_xlo);
    cudaGetSymbolAddress((void**)&ahi, g_ahi);
    cudaGetSymbolAddress((void**)&alo, g_alo);
    cudaGetSymbolAddress((void**)&bqkv, g_bqkv);
    cudaGetSymbolAddress((void**)&bprojt, g_bproj);

    cudaFuncSetAttribute(gemm_hmma_kernel<true>,
                         cudaFuncAttributeMaxDynamicSharedMemorySize, GEMM_SMEM);
    cudaFuncSetAttribute(gemm_hmma_kernel<false>,
                         cudaFuncAttributeMaxDynamicSharedMemorySize, GEMM_SMEM);
    cudaFuncSetAttribute(ctx_hmma_kernel,
                         cudaFuncAttributeMaxDynamicSharedMemorySize, CTX_SMEM);
    cudaFuncSetAttribute(attn_hmma_kernel,
                         cudaFuncAttributeMaxDynamicSharedMemorySize, ATTN_SMEM);

    // 0) conversions
    split_kernel<<<(Mrows * Cdim / 4 + 255) / 256, 256>>>(x, xhi, xlo,
                                                          Mrows * Cdim / 4);
    build_bt_kernel<<<dim3(ThreeC / 32, Cdim / 32), dim3(32, 8)>>>(Wqkv, bqkv, ThreeC);
    build_bt_kernel<<<dim3(Cdim / 32, Cdim / 32), dim3(32, 8)>>>(Wproj, bprojt, Cdim);

    // 1) qkv GEMM -> split bf16 q/k/v directly
    gemm_hmma_kernel<true><<<dim3(ThreeC / BN, Mrows / BM), 512, GEMM_SMEM>>>(
        xhi, xlo, bqkv, nullptr, 0, nullptr);

    // 2) context partials on tensor cores (+ exp sums)
    ctx_hmma_kernel<<<dim3(BH, NSPLIT), 128, CTX_SMEM>>>();

    // 3) reduce + normalize + split ctx^T
    ctx_reduce_kernel<<<(BH * Dd * Dd + 255) / 256, 256>>>();

    // 4) attn = q @ ctx on tensor cores -> ahi/alo
    attn_hmma_kernel<<<dim3(BH, Nseq / 128), 128, ATTN_SMEM>>>();

    // 5) out = attn @ Wproj + bias
    gemm_hmma_kernel<false><<<dim3(Cdim / BN, Mrows / BM), 512, GEMM_SMEM>>>(
        ahi, alo, bprojt, out, Cdim, bproj);
}

// round 10
// speedup vs baseline: 1.0505x; 1.0505x over previous
#include <cuda_runtime.h>
#include <cuda_bf16.h>
#include <cstdint>

// Problem constants
#define Bdim 8
#define Nseq 4096
#define Cdim 768
#define Hh   12
#define Dd   64
#define Mrows (Bdim * Nseq)      // 32768
#define ThreeC (3 * Cdim)        // 2304
#define BH (Bdim * Hh)           // 96
#define NSPLIT 4
#define KSPLIT 2304              // K' = 3*768 (hi/hi/lo folded split)

// GEMM tiling: BM=64, BN=256, BK=32; 256 threads; 2 CTAs/SM
#define BM 64
#define BN 256
#define BKK 32
#define KT2 (KSPLIT / BKK)       // 72
#define ROWB 80                  // smem row stride bytes (64B data + 16B pad)
#define ATILE (BM * ROWB)        // 5120
#define BTILE (BN * ROWB)        // 20480
#define STG (ATILE + BTILE)      // 25600
#define NSTAGE 3
#define GEMM_SMEM (NSTAGE * STG) // 76800  (x2 CTAs = 153600 <= 227KB)

// ---------------------------------------------------------------------------
// Scratch (device globals -- no allocation allowed)
// ---------------------------------------------------------------------------
__device__ float          g_qkv[(size_t)Mrows * ThreeC];   // 302 MB fp32
__device__ __nv_bfloat16  g_xhi[(size_t)Mrows * Cdim];
__device__ __nv_bfloat16  g_xlo[(size_t)Mrows * Cdim];
__device__ __nv_bfloat16  g_ahi[(size_t)Mrows * Cdim];
__device__ __nv_bfloat16  g_alo[(size_t)Mrows * Cdim];
__device__ __nv_bfloat16  g_bqkv[(size_t)ThreeC * KSPLIT]; // Bt [2304][2304]
__device__ __nv_bfloat16  g_bproj[(size_t)Cdim * KSPLIT];  // Bt [768][2304]
__device__ float g_psum[NSPLIT * BH * Dd];
__device__ float g_ctxp[NSPLIT * BH * Dd * Dd];
__device__ float g_ctx[BH * Dd * Dd];

// ---------------------------------------------------------------------------
// PTX helpers (arch-portable: cp.async + ldmatrix + mma.sync only)
// ---------------------------------------------------------------------------
__device__ __forceinline__ uint32_t smem_u32_of(const void* p) {
    uint32_t a;
    asm("{ .reg .u64 t; cvta.to.shared.u64 t, %1; cvt.u32.u64 %0, t; }"
        : "=r"(a) : "l"(p));
    return a;
}

__device__ __forceinline__ void cp_async16(uint32_t dst, const void* src) {
    asm volatile("cp.async.cg.shared.global [%0], [%1], 16;\n"
                 :: "r"(dst), "l"(src) : "memory");
}
#define CP_COMMIT() asm volatile("cp.async.commit_group;" ::: "memory")
#define CP_WAIT1()  asm volatile("cp.async.wait_group 1;" ::: "memory")
#define CP_WAIT0()  asm volatile("cp.async.wait_group 0;" ::: "memory")

__device__ __forceinline__ void ldmatrix_x4(uint32_t* r, uint32_t addr) {
    asm volatile(
        "ldmatrix.sync.aligned.m8n8.x4.shared.b16 {%0,%1,%2,%3}, [%4];"
        : "=r"(r[0]), "=r"(r[1]), "=r"(r[2]), "=r"(r[3]) : "r"(addr));
}

__device__ __forceinline__ void mma16816(float* d, const uint32_t* a,
                                         const uint32_t* b) {
    asm volatile(
        "mma.sync.aligned.m16n8k16.row.col.f32.bf16.bf16.f32 "
        "{%0,%1,%2,%3}, {%4,%5,%6,%7}, {%8,%9}, {%0,%1,%2,%3};"
        : "+f"(d[0]), "+f"(d[1]), "+f"(d[2]), "+f"(d[3])
        : "r"(a[0]), "r"(a[1]), "r"(a[2]), "r"(a[3]), "r"(b[0]), "r"(b[1]));
}

// ---------------------------------------------------------------------------
// GEMM: C[M, Ntot] fp32 = split-bf16 A'' (M x 2304) @ B''t (Ntot x 2304)^T
// A'' K-chunks: kt in [0,24)x2 = hi cols, [48,72) = lo cols.
// Bt rows pre-built as [hi | lo | hi].
// BM=64, BN=256, BK=32. 256 threads, warp grid 2(m) x 4(n), warp tile 32x64.
// 3-stage cp.async pipeline; 2 CTAs/SM for cross-CTA latency hiding.
// ---------------------------------------------------------------------------
__device__ __forceinline__ void gemm_load_stage(
    const __nv_bfloat16* __restrict__ Ahi, const __nv_bfloat16* __restrict__ Alo,
    const __nv_bfloat16* __restrict__ Bt,
    size_t m0, size_t n0, int kt, int stage, uint32_t sb, int tid)
{
    int blk = kt / 24;
    const __nv_bfloat16* asrc = (blk < 2) ? Ahi : Alo;
    int acol = (kt - blk * 24) * BKK;
    int bcol = kt * BKK;
    uint32_t as = sb + stage * STG;
    uint32_t bs = as + ATILE;
    int lr = tid >> 2;          // 0..63
    int lc = tid & 3;           // 16B chunk within 64B row

    cp_async16(as + lr * ROWB + lc * 16,
               asrc + (m0 + lr) * Cdim + acol + lc * 8);
    #pragma unroll
    for (int i = 0; i < 4; i++) {
        int r = lr + i * 64;
        cp_async16(bs + r * ROWB + lc * 16,
                   Bt + (n0 + r) * (size_t)KSPLIT + bcol + lc * 8);
    }
    CP_COMMIT();
}

__global__ __launch_bounds__(256, 2) void gemm_hmma_kernel(
    const __nv_bfloat16* __restrict__ Ahi,
    const __nv_bfloat16* __restrict__ Alo,
    const __nv_bfloat16* __restrict__ Bt,
    float* __restrict__ Cm, int ldc,
    const float* __restrict__ bias)
{
    extern __shared__ char smem[];
    uint32_t sb = smem_u32_of(smem);
    int tid = threadIdx.x;
    int lane = tid & 31, wid = tid >> 5;
    int wm = wid >> 2, wn = wid & 3;     // warp grid 2 (m) x 4 (n)

    size_t m0 = (size_t)blockIdx.y * BM;
    size_t n0 = (size_t)blockIdx.x * BN;

    // Per-thread ldmatrix byte offsets (within a stage)
    uint32_t a_off = (uint32_t)(wm * 32 + (lane & 15)) * ROWB + ((lane >> 4) << 4);
    uint32_t b_off = ATILE +
        (uint32_t)(wn * 64 + (lane & 7) + ((lane >> 4) << 3)) * ROWB +
        ((lane & 8) << 1);

    float acc[2][8][4];
    #pragma unroll
    for (int mf = 0; mf < 2; mf++)
        #pragma unroll
        for (int nf = 0; nf < 8; nf++)
            #pragma unroll
            for (int c = 0; c < 4; c++) acc[mf][nf][c] = 0.f;

    // Prologue: 2 stages in flight
    gemm_load_stage(Ahi, Alo, Bt, m0, n0, 0, 0, sb, tid);
    gemm_load_stage(Ahi, Alo, Bt, m0, n0, 1, 1, sb, tid);

    for (int kt = 0; kt < KT2; kt++) {
        if (kt < KT2 - 1) CP_WAIT1(); else CP_WAIT0();
        __syncthreads();
        if (kt + 2 < KT2)
            gemm_load_stage(Ahi, Alo, Bt, m0, n0, kt + 2, (kt + 2) % NSTAGE, sb, tid);

        uint32_t stg = sb + (kt % NSTAGE) * STG;
        #pragma unroll
        for (int ks = 0; ks < 2; ks++) {
            uint32_t aF[2][4];
            uint32_t bF[4][4];
            #pragma unroll
            for (int mf = 0; mf < 2; mf++)
                ldmatrix_x4(aF[mf], stg + a_off + mf * (16 * ROWB) + ks * 32);
            #pragma unroll
            for (int nf2 = 0; nf2 < 4; nf2++)
                ldmatrix_x4(bF[nf2], stg + b_off + nf2 * (16 * ROWB) + ks * 32);
            #pragma unroll
            for (int mf = 0; mf < 2; mf++)
                #pragma unroll
                for (int nf = 0; nf < 8; nf++)
                    mma16816(acc[mf][nf], aF[mf], &bF[nf >> 1][(nf & 1) * 2]);
        }
    }

    // Epilogue: direct fp32 stores
    #pragma unroll
    for (int mf = 0; mf < 2; mf++) {
        size_t row = m0 + wm * 32 + mf * 16 + (lane >> 2);
        #pragma unroll
        for (int nf = 0; nf < 8; nf++) {
            int col = (int)n0 + wn * 64 + nf * 8 + (lane & 3) * 2;
            float b0 = 0.f, b1 = 0.f;
            if (bias) { b0 = bias[col]; b1 = bias[col + 1]; }
            float2 v0; v0.x = acc[mf][nf][0] + b0; v0.y = acc[mf][nf][1] + b1;
            float2 v1; v1.x = acc[mf][nf][2] + b0; v1.y = acc[mf][nf][3] + b1;
            *reinterpret_cast<float2*>(&Cm[row * (size_t)ldc + col]) = v0;
            *reinterpret_cast<float2*>(&Cm[(row + 8) * (size_t)ldc + col]) = v1;
        }
    }
}

// ---------------------------------------------------------------------------
// Split fp32 -> (hi, lo) bf16
// ---------------------------------------------------------------------------
__device__ __forceinline__ void split2(float v, __nv_bfloat16& h, __nv_bfloat16& l) {
    h = __float2bfloat16(v);
    l = __float2bfloat16(v - __bfloat162float(h));
}

__global__ __launch_bounds__(256) void split_kernel(
    const float* __restrict__ in, __nv_bfloat16* __restrict__ hi,
    __nv_bfloat16* __restrict__ lo, int n4)
{
    int i = blockIdx.x * 256 + threadIdx.x;
    if (i >= n4) return;
    float4 v = reinterpret_cast<const float4*>(in)[i];
    __nv_bfloat16 h0, h1, h2, h3, l0, l1, l2, l3;
    split2(v.x, h0, l0); split2(v.y, h1, l1);
    split2(v.z, h2, l2); split2(v.w, h3, l3);
    __nv_bfloat162* hp = reinterpret_cast<__nv_bfloat162*>(hi) + i * 2;
    __nv_bfloat162* lp = reinterpret_cast<__nv_bfloat162*>(lo) + i * 2;
    __nv_bfloat162 a; a.x = h0; a.y = h1;
    __nv_bfloat162 b; b.x = h2; b.y = h3;
    __nv_bfloat162 c; c.x = l0; c.y = l1;
    __nv_bfloat162 d; d.x = l2; d.y = l3;
    hp[0] = a; hp[1] = b; lp[0] = c; lp[1] = d;
}

// ---------------------------------------------------------------------------
// Build transposed split weight: W [768 x Nn] fp32 -> Bt [Nn x 2304] bf16
// rows of Bt: cols [0,768)=hi, [768,1536)=lo, [1536,2304)=hi
// ---------------------------------------------------------------------------
__global__ __launch_bounds__(256) void build_bt_kernel(
    const float* __restrict__ W, __nv_bfloat16* __restrict__ Bt, int Nn)
{
    __shared__ float t[32][33];
    int n0 = blockIdx.x * 32, k0 = blockIdx.y * 32;
    int tx = threadIdx.x, ty = threadIdx.y;   // (32, 8)
    #pragma unroll
    for (int j = 0; j < 32; j += 8)
        t[ty + j][tx] = W[(size_t)(k0 + ty + j) * Nn + n0 + tx];
    __syncthreads();
    #pragma unroll
    for (int j = 0; j < 32; j += 8) {
        int n = n0 + ty + j, k = k0 + tx;
        float v = t[tx][ty + j];
        __nv_bfloat16 h, l;
        split2(v, h, l);
        size_t base = (size_t)n * KSPLIT;
        Bt[base + k] = h;
        Bt[base + 768 + k] = l;
        Bt[base + 1536 + k] = h;
    }
}

// ---------------------------------------------------------------------------
// Partial context + partial exp-sums (no max subtraction: k ~ N(0,1), safe).
// ctxp[split][bh][d][e] = sum_{n in split} exp(k[n,d]) * v[n,e]
// psum[split][bh][d]    = sum_{n in split} exp(k[n,d])
// ---------------------------------------------------------------------------
__global__ __launch_bounds__(256) void ctx_partial_kernel()
{
    int bh = blockIdx.x, split = blockIdx.y;
    int b = bh / Hh, h = bh - b * Hh;
    int n_start = split * (Nseq / NSPLIT);

    const float* kbase = g_qkv + (size_t)b * Nseq * ThreeC + Cdim + h * Dd;
    const float* vbase = g_qkv + (size_t)b * Nseq * ThreeC + 2 * Cdim + h * Dd;

    __shared__ float ks[16][68];
    __shared__ float vs[16][68];

    int tid = threadIdx.x;
    int lr = tid >> 4, lc = (tid & 15) * 4;
    int rowd = (tid >> 4) * 4, cole = (tid & 15) * 4;

    float acc[4][4];
    #pragma unroll
    for (int i = 0; i < 4; i++)
        #pragma unroll
        for (int j = 0; j < 4; j++) acc[i][j] = 0.f;
    float sum4[4] = {0.f, 0.f, 0.f, 0.f};

    for (int nt = 0; nt < Nseq / NSPLIT; nt += 16) {
        size_t off = (size_t)(n_start + nt + lr) * ThreeC + lc;
        float4 kv = *reinterpret_cast<const float4*>(&kbase[off]);
        float e0 = __expf(kv.x), e1 = __expf(kv.y);
        float e2 = __expf(kv.z), e3 = __expf(kv.w);
        ks[lr][lc + 0] = e0; ks[lr][lc + 1] = e1;
        ks[lr][lc + 2] = e2; ks[lr][lc + 3] = e3;
        sum4[0] += e0; sum4[1] += e1; sum4[2] += e2; sum4[3] += e3;
        *reinterpret_cast<float4*>(&vs[lr][lc]) =
            *reinterpret_cast<const float4*>(&vbase[off]);
        __syncthreads();

        #pragma unroll
        for (int kk = 0; kk < 16; kk++) {
            float4 a = *reinterpret_cast<const float4*>(&ks[kk][rowd]);
            float4 bb = *reinterpret_cast<const float4*>(&vs[kk][cole]);
            float af[4] = {a.x, a.y, a.z, a.w};
            float bv[4] = {bb.x, bb.y, bb.z, bb.w};
            #pragma unroll
            for (int i = 0; i < 4; i++)
                #pragma unroll
                for (int j = 0; j < 4; j++)
                    acc[i][j] += af[i] * bv[j];
        }
        __syncthreads();
    }

    float* outp = g_ctxp + (size_t)(split * BH + bh) * (Dd * Dd);
    #pragma unroll
    for (int i = 0; i < 4; i++) {
        float4 o;
        o.x = acc[i][0]; o.y = acc[i][1]; o.z = acc[i][2]; o.w = acc[i][3];
        *reinterpret_cast<float4*>(&outp[(rowd + i) * Dd + cole]) = o;
    }

    // Reduce per-column exp sums (16 row-groups) via smem
    ks[lr][lc + 0] = sum4[0]; ks[lr][lc + 1] = sum4[1];
    ks[lr][lc + 2] = sum4[2]; ks[lr][lc + 3] = sum4[3];
    __syncthreads();
    if (tid < 64) {
        float s = 0.f;
        #pragma unroll
        for (int r = 0; r < 16; r++) s += ks[r][tid];
        g_psum[(split * BH + bh) * Dd + tid] = s;
    }
}

__global__ __launch_bounds__(256) void ctx_reduce_kernel()
{
    int idx = blockIdx.x * 256 + threadIdx.x;
    const int total = BH * Dd * Dd;
    if (idx >= total) return;
    int bh = idx >> 12;
    int d = (idx & 4095) >> 6;
    float ksum = 0.f;
    float s = 0.f;
    #pragma unroll
    for (int sp = 0; sp < NSPLIT; sp++) {
        ksum += g_psum[(sp * BH + bh) * Dd + d];
        s += g_ctxp[(size_t)sp * total + idx];
    }
    g_ctx[idx] = s / ksum;
}

// ---------------------------------------------------------------------------
// attn = q @ ctx -> write bf16 hi/lo directly (A-side of GEMM2)
// ---------------------------------------------------------------------------
__global__ __launch_bounds__(256) void attn_out_kernel()
{
    int bh = blockIdx.x, nb = blockIdx.y;
    int b = bh / Hh, h = bh - b * Hh;
    int n0 = nb * 128;

    __shared__ float q_s[128][17];
    __shared__ float ctx_s[16][64];

    const float* qbase = g_qkv + (size_t)b * Nseq * ThreeC + h * Dd;
    const float* cbase = g_ctx + (size_t)bh * (Dd * Dd);

    int tid = threadIdx.x;
    int rowb = (tid >> 4) * 8;
    int col  = (tid & 15) * 4;

    float acc[8][4];
    #pragma unroll
    for (int i = 0; i < 8; i++)
        #pragma unroll
        for (int j = 0; j < 4; j++) acc[i][j] = 0.f;

    for (int dc = 0; dc < Dd; dc += 16) {
        #pragma unroll
        for (int t = 0; t < 2; t++) {
            int idx = tid + t * 256;
            int r = idx >> 2;
            int c4 = (idx & 3) * 4;
            float4 qv = *reinterpret_cast<const float4*>(
                &qbase[(size_t)(n0 + r) * ThreeC + dc + c4]);
            q_s[r][c4 + 0] = qv.x; q_s[r][c4 + 1] = qv.y;
            q_s[r][c4 + 2] = qv.z; q_s[r][c4 + 3] = qv.w;
        }
        {
            int r = tid >> 4;
            int c4 = (tid & 15) * 4;
            *reinterpret_cast<float4*>(&ctx_s[r][c4]) =
                *reinterpret_cast<const float4*>(&cbase[(size_t)(dc + r) * Dd + c4]);
        }
        __syncthreads();

        #pragma unroll
        for (int dd = 0; dd < 16; dd++) {
            float4 cf = *reinterpret_cast<const float4*>(&ctx_s[dd][col]);
            float cv[4] = {cf.x, cf.y, cf.z, cf.w};
            #pragma unroll
            for (int i = 0; i < 8; i++) {
                float qv = q_s[rowb + i][dd];
                #pragma unroll
                for (int j = 0; j < 4; j++) acc[i][j] += qv * cv[j];
            }
        }
        __syncthreads();
    }

    #pragma unroll
    for (int i = 0; i < 8; i++) {
        size_t base = ((size_t)b * Nseq + n0 + rowb + i) * Cdim + h * Dd + col;
        __nv_bfloat16 h0, h1, h2, h3, l0, l1, l2, l3;
        split2(acc[i][0], h0, l0); split2(acc[i][1], h1, l1);
        split2(acc[i][2], h2, l2); split2(acc[i][3], h3, l3);
        __nv_bfloat162* hp = reinterpret_cast<__nv_bfloat162*>(&g_ahi[base]);
        __nv_bfloat162* lp = reinterpret_cast<__nv_bfloat162*>(&g_alo[base]);
        __nv_bfloat162 p0; p0.x = h0; p0.y = h1;
        __nv_bfloat162 p1; p1.x = h2; p1.y = h3;
        __nv_bfloat162 p2; p2.x = l0; p2.y = l1;
        __nv_bfloat162 p3; p3.x = l2; p3.y = l3;
        hp[0] = p0; hp[1] = p1; lp[0] = p2; lp[1] = p3;
    }
}

// ---------------------------------------------------------------------------
extern "C" void kernel_launch(void* const* d_in, const int* in_sizes, int n_in,
                              void* d_out, int out_size)
{
    const float* x     = (const float*)d_in[0];   // [8,4096,768]
    const float* Wqkv  = (const float*)d_in[1];   // [768,2304]
    const float* Wproj = (const float*)d_in[2];   // [768,768]
    const float* bproj = (const float*)d_in[3];   // [768]
    float* out = (float*)d_out;

    float *qkv_ptr;
    __nv_bfloat16 *xhi, *xlo, *ahi, *alo, *bqkv, *bprojt;
    cudaGetSymbolAddress((void**)&qkv_ptr, g_qkv);
    cudaGetSymbolAddress((void**)&xhi, g_xhi);
    cudaGetSymbolAddress((void**)&xlo, g_xlo);
    cudaGetSymbolAddress((void**)&ahi, g_ahi);
    cudaGetSymbolAddress((void**)&alo, g_alo);
    cudaGetSymbolAddress((void**)&bqkv, g_bqkv);
    cudaGetSymbolAddress((void**)&bprojt, g_bproj);

    cudaFuncSetAttribute(gemm_hmma_kernel,
                         cudaFuncAttributeMaxDynamicSharedMemorySize, GEMM_SMEM);

    // 0) conversions
    split_kernel<<<(Mrows * Cdim / 4 + 255) / 256, 256>>>(x, xhi, xlo,
                                                          Mrows * Cdim / 4);
    build_bt_kernel<<<dim3(ThreeC / 32, Cdim / 32), dim3(32, 8)>>>(Wqkv, bqkv, ThreeC);
    build_bt_kernel<<<dim3(Cdim / 32, Cdim / 32), dim3(32, 8)>>>(Wproj, bprojt, Cdim);

    // 1) qkv = x @ Wqkv  (HMMA tensor cores, split bf16)
    gemm_hmma_kernel<<<dim3(ThreeC / BN, Mrows / BM), 256, GEMM_SMEM>>>(
        xhi, xlo, bqkv, qkv_ptr, ThreeC, nullptr);

    // 2-3) fused context + exp-sum partials, then reduce
    ctx_partial_kernel<<<dim3(BH, NSPLIT), 256>>>();
    ctx_reduce_kernel<<<(BH * Dd * Dd + 255) / 256, 256>>>();

    // 4) attn = q @ ctx -> bf16 hi/lo
    attn_out_kernel<<<dim3(BH, Nseq / 128), 256>>>();

    // 5) out = attn @ Wproj + bias  (HMMA tensor cores, split bf16)
    gemm_hmma_kernel<<<dim3(Cdim / BN, Mrows / BM), 256, GEMM_SMEM>>>(
        ahi, alo, bprojt, out, Cdim, bproj);
}

// round 11
// speedup vs baseline: 1.3594x; 1.2940x over previous
#include <cuda_runtime.h>
#include <cuda_fp16.h>
#include <cuda_bf16.h>
#include <cstdint>

// Problem constants
#define Bdim 8
#define Nseq 4096
#define Cdim 768
#define Hh   12
#define Dd   64
#define Mrows (Bdim * Nseq)      // 32768
#define ThreeC (3 * Cdim)        // 2304
#define BH (Bdim * Hh)           // 96
#define NSPLIT 4

// K' for the two GEMMs (in 32-wide tiles: 24 per 768-block)
#define KT_QKV  48               // K' = 1536: A''=[xh|xh], B''=[Bh;Bl]
#define KT_PROJ 72               // K' = 2304: A''=[ah|ah|al], B''=[Bh;Bl;Bh]

// GEMM tiling (R5 proven config)
#define BM 128
#define BN 256
#define BKK 32
#define ROWB 80                  // smem row stride bytes (64B data + 16B pad)
#define ATILE (BM * ROWB)
#define BTILE (BN * ROWB)
#define STG (ATILE + BTILE)      // 30720
#define NSTAGE 4
#define GEMM_SMEM (NSTAGE * STG) // 122880

// ---------------------------------------------------------------------------
// Scratch (device globals -- no allocation allowed)
// ---------------------------------------------------------------------------
__device__ float   g_qkv[(size_t)Mrows * ThreeC];     // 302 MB fp32
__device__ __half  g_xh[(size_t)Mrows * Cdim];        // x rounded to fp16
__device__ __half  g_ah[(size_t)Mrows * Cdim];        // attn hi
__device__ __half  g_al[(size_t)Mrows * Cdim];        // attn lo
__device__ __half  g_bqkv[(size_t)ThreeC * 1536];     // Wqkv^T split [Bh|Bl]
__device__ __half  g_bproj[(size_t)Cdim * ThreeC];    // Wproj^T split [Bh|Bl|Bh]
__device__ float g_psum[NSPLIT * BH * Dd];
__device__ float g_ctxp[NSPLIT * BH * Dd * Dd];
__device__ float g_ctx[BH * Dd * Dd];

// ---------------------------------------------------------------------------
// PTX helpers (arch-portable: cp.async + ldmatrix + mma.sync only)
// ---------------------------------------------------------------------------
__device__ __forceinline__ uint32_t smem_u32_of(const void* p) {
    uint32_t a;
    asm("{ .reg .u64 t; cvta.to.shared.u64 t, %1; cvt.u32.u64 %0, t; }"
        : "=r"(a) : "l"(p));
    return a;
}

__device__ __forceinline__ void cp_async16(uint32_t dst, const void* src) {
    asm volatile("cp.async.cg.shared.global [%0], [%1], 16;\n"
                 :: "r"(dst), "l"(src) : "memory");
}
#define CP_COMMIT() asm volatile("cp.async.commit_group;" ::: "memory")
#define CP_WAIT2()  asm volatile("cp.async.wait_group 2;" ::: "memory")
#define CP_WAIT1()  asm volatile("cp.async.wait_group 1;" ::: "memory")
#define CP_WAIT0()  asm volatile("cp.async.wait_group 0;" ::: "memory")

__device__ __forceinline__ void ldmatrix_x4(uint32_t* r, uint32_t addr) {
    asm volatile(
        "ldmatrix.sync.aligned.m8n8.x4.shared.b16 {%0,%1,%2,%3}, [%4];"
        : "=r"(r[0]), "=r"(r[1]), "=r"(r[2]), "=r"(r[3]) : "r"(addr));
}

__device__ __forceinline__ void mma16816(float* d, const uint32_t* a,
                                         const uint32_t* b) {
    asm volatile(
        "mma.sync.aligned.m16n8k16.row.col.f32.f16.f16.f32 "
        "{%0,%1,%2,%3}, {%4,%5,%6,%7}, {%8,%9}, {%0,%1,%2,%3};"
        : "+f"(d[0]), "+f"(d[1]), "+f"(d[2]), "+f"(d[3])
        : "r"(a[0]), "r"(a[1]), "r"(a[2]), "r"(a[3]), "r"(b[0]), "r"(b[1]));
}

__device__ __forceinline__ void split2h(float v, __half& h, __half& l) {
    h = __float2half(v);
    l = __float2half(v - __half2float(h));
}

// ---------------------------------------------------------------------------
// GEMM: C[M, Ntot] fp32 = fp16 A'' (M x 32*KTT) @ B''t (Ntot x 32*KTT)^T
// Per-768 blocks: blk 0,1 read Ahi; blk 2 reads Alo.
//   KTT=48: A''=[Ahi|Ahi],      B''t rows = [Bh | Bl]
//   KTT=72: A''=[Ahi|Ahi|Alo],  B''t rows = [Bh | Bl | Bh]
// BM=128 BN=256 BK=32, 512 threads (warp 4m x 4n), 4-stage cp.async.
// ---------------------------------------------------------------------------
__device__ __forceinline__ void gemm_load_stage(
    const __half* __restrict__ Ahi, const __half* __restrict__ Alo,
    const __half* __restrict__ Bt, int ldb,
    size_t m0, size_t n0, int kt, int stage, uint32_t sb, int tid)
{
    int blk = kt / 24;
    const __half* asrc = (blk < 2) ? Ahi : Alo;
    int acol = (kt - blk * 24) * BKK;
    int bcol = kt * BKK;
    uint32_t as = sb + stage * STG;
    uint32_t bs = as + ATILE;
    int lr = tid >> 2;
    int lc = tid & 3;

    cp_async16(as + lr * ROWB + lc * 16,
               asrc + (m0 + lr) * Cdim + acol + lc * 8);
    cp_async16(bs + lr * ROWB + lc * 16,
               Bt + (n0 + lr) * (size_t)ldb + bcol + lc * 8);
    cp_async16(bs + (lr + 128) * ROWB + lc * 16,
               Bt + (n0 + lr + 128) * (size_t)ldb + bcol + lc * 8);
    CP_COMMIT();
}

template <int KTT>
__global__ __launch_bounds__(512, 1) void gemm_hmma_kernel(
    const __half* __restrict__ Ahi,
    const __half* __restrict__ Alo,
    const __half* __restrict__ Bt, int ldb,
    float* __restrict__ Cm, int ldc,
    const float* __restrict__ bias)
{
    extern __shared__ char smem[];
    uint32_t sb = smem_u32_of(smem);
    int tid = threadIdx.x;
    int lane = tid & 31, wid = tid >> 5;
    int wm = wid >> 2, wn = wid & 3;

    size_t m0 = (size_t)blockIdx.y * BM;
    size_t n0 = (size_t)blockIdx.x * BN;

    uint32_t a_off = (uint32_t)(wm * 32 + (lane & 15)) * ROWB + ((lane >> 4) << 4);
    uint32_t b_off = ATILE +
        (uint32_t)(wn * 64 + (lane & 7) + ((lane >> 4) << 3)) * ROWB +
        ((lane & 8) << 1);

    float acc[2][8][4];
    #pragma unroll
    for (int mf = 0; mf < 2; mf++)
        #pragma unroll
        for (int nf = 0; nf < 8; nf++)
            #pragma unroll
            for (int c = 0; c < 4; c++) acc[mf][nf][c] = 0.f;

    gemm_load_stage(Ahi, Alo, Bt, ldb, m0, n0, 0, 0, sb, tid);
    gemm_load_stage(Ahi, Alo, Bt, ldb, m0, n0, 1, 1, sb, tid);
    gemm_load_stage(Ahi, Alo, Bt, ldb, m0, n0, 2, 2, sb, tid);

    for (int kt = 0; kt < KTT; kt++) {
        int rem = KTT - 1 - kt;
        if (rem >= 2) CP_WAIT2();
        else if (rem == 1) CP_WAIT1();
        else CP_WAIT0();
        __syncthreads();
        if (kt + 3 < KTT)
            gemm_load_stage(Ahi, Alo, Bt, ldb, m0, n0, kt + 3, (kt + 3) & 3, sb, tid);

        uint32_t stg = sb + (kt & 3) * STG;
        #pragma unroll
        for (int ks = 0; ks < 2; ks++) {
            uint32_t aF[2][4];
            uint32_t bF[4][4];
            #pragma unroll
            for (int mf = 0; mf < 2; mf++)
                ldmatrix_x4(aF[mf], stg + a_off + mf * (16 * ROWB) + ks * 32);
            #pragma unroll
            for (int nf2 = 0; nf2 < 4; nf2++)
                ldmatrix_x4(bF[nf2], stg + b_off + nf2 * (16 * ROWB) + ks * 32);
            #pragma unroll
            for (int mf = 0; mf < 2; mf++)
                #pragma unroll
                for (int nf = 0; nf < 8; nf++)
                    mma16816(acc[mf][nf], aF[mf], &bF[nf >> 1][(nf & 1) * 2]);
        }
    }

    #pragma unroll
    for (int mf = 0; mf < 2; mf++) {
        size_t row = m0 + wm * 32 + mf * 16 + (lane >> 2);
        #pragma unroll
        for (int nf = 0; nf < 8; nf++) {
            int col = (int)n0 + wn * 64 + nf * 8 + (lane & 3) * 2;
            float b0 = 0.f, b1 = 0.f;
            if (bias) { b0 = bias[col]; b1 = bias[col + 1]; }
            float2 v0; v0.x = acc[mf][nf][0] + b0; v0.y = acc[mf][nf][1] + b1;
            float2 v1; v1.x = acc[mf][nf][2] + b0; v1.y = acc[mf][nf][3] + b1;
            *reinterpret_cast<float2*>(&Cm[row * (size_t)ldc + col]) = v0;
            *reinterpret_cast<float2*>(&Cm[(row + 8) * (size_t)ldc + col]) = v1;
        }
    }
}

// ---------------------------------------------------------------------------
// Round x fp32 -> fp16 (single term)
// ---------------------------------------------------------------------------
__global__ __launch_bounds__(256) void round_kernel(
    const float* __restrict__ in, __half* __restrict__ hi, int n4)
{
    int i = blockIdx.x * 256 + threadIdx.x;
    if (i >= n4) return;
    float4 v = reinterpret_cast<const float4*>(in)[i];
    __half2* hp = reinterpret_cast<__half2*>(hi) + i * 2;
    __half2 a; a.x = __float2half(v.x); a.y = __float2half(v.y);
    __half2 b; b.x = __float2half(v.z); b.y = __float2half(v.w);
    hp[0] = a; hp[1] = b;
}

// ---------------------------------------------------------------------------
// Build transposed split weight: W [768 x Nn] fp32 -> Bt [Nn x ldb] fp16
// row layout: [Bh(768) | Bl(768)] and, if three==1, | Bh(768) ]
// ---------------------------------------------------------------------------
__global__ __launch_bounds__(256) void build_bt_kernel(
    const float* __restrict__ W, __half* __restrict__ Bt, int Nn,
    int ldb, int three)
{
    __shared__ float t[32][33];
    int n0 = blockIdx.x * 32, k0 = blockIdx.y * 32;
    int tx = threadIdx.x, ty = threadIdx.y;   // (32, 8)
    #pragma unroll
    for (int j = 0; j < 32; j += 8)
        t[ty + j][tx] = W[(size_t)(k0 + ty + j) * Nn + n0 + tx];
    __syncthreads();
    #pragma unroll
    for (int j = 0; j < 32; j += 8) {
        int n = n0 + ty + j, k = k0 + tx;
        float v = t[tx][ty + j];
        __half h, l;
        split2h(v, h, l);
        size_t base = (size_t)n * ldb;
        Bt[base + k] = h;
        Bt[base + 768 + k] = l;
        if (three) Bt[base + 1536 + k] = h;
    }
}

// ---------------------------------------------------------------------------
// Partial context + partial exp-sums (no max subtraction: k ~ N(0,1), safe).
// ---------------------------------------------------------------------------
__global__ __launch_bounds__(256) void ctx_partial_kernel()
{
    int bh = blockIdx.x, split = blockIdx.y;
    int b = bh / Hh, h = bh - b * Hh;
    int n_start = split * (Nseq / NSPLIT);

    const float* kbase = g_qkv + (size_t)b * Nseq * ThreeC + Cdim + h * Dd;
    const float* vbase = g_qkv + (size_t)b * Nseq * ThreeC + 2 * Cdim + h * Dd;

    __shared__ float ks[16][68];
    __shared__ float vs[16][68];

    int tid = threadIdx.x;
    int lr = tid >> 4, lc = (tid & 15) * 4;
    int rowd = (tid >> 4) * 4, cole = (tid & 15) * 4;

    float acc[4][4];
    #pragma unroll
    for (int i = 0; i < 4; i++)
        #pragma unroll
        for (int j = 0; j < 4; j++) acc[i][j] = 0.f;
    float sum4[4] = {0.f, 0.f, 0.f, 0.f};

    for (int nt = 0; nt < Nseq / NSPLIT; nt += 16) {
        size_t off = (size_t)(n_start + nt + lr) * ThreeC + lc;
        float4 kv = *reinterpret_cast<const float4*>(&kbase[off]);
        float e0 = __expf(kv.x), e1 = __expf(kv.y);
        float e2 = __expf(kv.z), e3 = __expf(kv.w);
        ks[lr][lc + 0] = e0; ks[lr][lc + 1] = e1;
        ks[lr][lc + 2] = e2; ks[lr][lc + 3] = e3;
        sum4[0] += e0; sum4[1] += e1; sum4[2] += e2; sum4[3] += e3;
        *reinterpret_cast<float4*>(&vs[lr][lc]) =
            *reinterpret_cast<const float4*>(&vbase[off]);
        __syncthreads();

        #pragma unroll
        for (int kk = 0; kk < 16; kk++) {
            float4 a = *reinterpret_cast<const float4*>(&ks[kk][rowd]);
            float4 bb = *reinterpret_cast<const float4*>(&vs[kk][cole]);
            float af[4] = {a.x, a.y, a.z, a.w};
            float bv[4] = {bb.x, bb.y, bb.z, bb.w};
            #pragma unroll
            for (int i = 0; i < 4; i++)
                #pragma unroll
                for (int j = 0; j < 4; j++)
                    acc[i][j] += af[i] * bv[j];
        }
        __syncthreads();
    }

    float* outp = g_ctxp + (size_t)(split * BH + bh) * (Dd * Dd);
    #pragma unroll
    for (int i = 0; i < 4; i++) {
        float4 o;
        o.x = acc[i][0]; o.y = acc[i][1]; o.z = acc[i][2]; o.w = acc[i][3];
        *reinterpret_cast<float4*>(&outp[(rowd + i) * Dd + cole]) = o;
    }

    ks[lr][lc + 0] = sum4[0]; ks[lr][lc + 1] = sum4[1];
    ks[lr][lc + 2] = sum4[2]; ks[lr][lc + 3] = sum4[3];
    __syncthreads();
    if (tid < 64) {
        float s = 0.f;
        #pragma unroll
        for (int r = 0; r < 16; r++) s += ks[r][tid];
        g_psum[(split * BH + bh) * Dd + tid] = s;
    }
}

__global__ __launch_bounds__(256) void ctx_reduce_kernel()
{
    int idx = blockIdx.x * 256 + threadIdx.x;
    const int total = BH * Dd * Dd;
    if (idx >= total) return;
    int bh = idx >> 12;
    int d = (idx & 4095) >> 6;
    float ksum = 0.f;
    float s = 0.f;
    #pragma unroll
    for (int sp = 0; sp < NSPLIT; sp++) {
        ksum += g_psum[(sp * BH + bh) * Dd + d];
        s += g_ctxp[(size_t)sp * total + idx];
    }
    g_ctx[idx] = s / ksum;
}

// ---------------------------------------------------------------------------
// attn = q @ ctx -> write fp16 hi/lo (A-side of GEMM2)
// ---------------------------------------------------------------------------
__global__ __launch_bounds__(256) void attn_out_kernel()
{
    int bh = blockIdx.x, nb = blockIdx.y;
    int b = bh / Hh, h = bh - b * Hh;
    int n0 = nb * 128;

    __shared__ float q_s[128][17];
    __shared__ float ctx_s[16][64];

    const float* qbase = g_qkv + (size_t)b * Nseq * ThreeC + h * Dd;
    const float* cbase = g_ctx + (size_t)bh * (Dd * Dd);

    int tid = threadIdx.x;
    int rowb = (tid >> 4) * 8;
    int col  = (tid & 15) * 4;

    float acc[8][4];
    #pragma unroll
    for (int i = 0; i < 8; i++)
        #pragma unroll
        for (int j = 0; j < 4; j++) acc[i][j] = 0.f;

    for (int dc = 0; dc < Dd; dc += 16) {
        #pragma unroll
        for (int t = 0; t < 2; t++) {
            int idx = tid + t * 256;
            int r = idx >> 2;
            int c4 = (idx & 3) * 4;
            float4 qv = *reinterpret_cast<const float4*>(
                &qbase[(size_t)(n0 + r) * ThreeC + dc + c4]);
            q_s[r][c4 + 0] = qv.x; q_s[r][c4 + 1] = qv.y;
            q_s[r][c4 + 2] = qv.z; q_s[r][c4 + 3] = qv.w;
        }
        {
            int r = tid >> 4;
            int c4 = (tid & 15) * 4;
            *reinterpret_cast<float4*>(&ctx_s[r][c4]) =
                *reinterpret_cast<const float4*>(&cbase[(size_t)(dc + r) * Dd + c4]);
        }
        __syncthreads();

        #pragma unroll
        for (int dd = 0; dd < 16; dd++) {
            float4 cf = *reinterpret_cast<const float4*>(&ctx_s[dd][col]);
            float cv[4] = {cf.x, cf.y, cf.z, cf.w};
            #pragma unroll
            for (int i = 0; i < 8; i++) {
                float qv = q_s[rowb + i][dd];
                #pragma unroll
                for (int j = 0; j < 4; j++) acc[i][j] += qv * cv[j];
            }
        }
        __syncthreads();
    }

    #pragma unroll
    for (int i = 0; i < 8; i++) {
        size_t base = ((size_t)b * Nseq + n0 + rowb + i) * Cdim + h * Dd + col;
        __half h0, h1, h2, h3, l0, l1, l2, l3;
        split2h(acc[i][0], h0, l0); split2h(acc[i][1], h1, l1);
        split2h(acc[i][2], h2, l2); split2h(acc[i][3], h3, l3);
        __half2* hp = reinterpret_cast<__half2*>(&g_ah[base]);
        __half2* lp = reinterpret_cast<__half2*>(&g_al[base]);
        __half2 p0; p0.x = h0; p0.y = h1;
        __half2 p1; p1.x = h2; p1.y = h3;
        __half2 p2; p2.x = l0; p2.y = l1;
        __half2 p3; p3.x = l2; p3.y = l3;
        hp[0] = p0; hp[1] = p1; lp[0] = p2; lp[1] = p3;
    }
}

// ---------------------------------------------------------------------------
extern "C" void kernel_launch(void* const* d_in, const int* in_sizes, int n_in,
                              void* d_out, int out_size)
{
    const float* x     = (const float*)d_in[0];   // [8,4096,768]
    const float* Wqkv  = (const float*)d_in[1];   // [768,2304]
    const float* Wproj = (const float*)d_in[2];   // [768,768]
    const float* bproj = (const float*)d_in[3];   // [768]
    float* out = (float*)d_out;

    float *qkv_ptr;
    __half *xh, *ah, *al, *bqkv, *bprojt;
    cudaGetSymbolAddress((void**)&qkv_ptr, g_qkv);
    cudaGetSymbolAddress((void**)&xh, g_xh);
    cudaGetSymbolAddress((void**)&ah, g_ah);
    cudaGetSymbolAddress((void**)&al, g_al);
    cudaGetSymbolAddress((void**)&bqkv, g_bqkv);
    cudaGetSymbolAddress((void**)&bprojt, g_bproj);

    cudaFuncSetAttribute(gemm_hmma_kernel<KT_QKV>,
                         cudaFuncAttributeMaxDynamicSharedMemorySize, GEMM_SMEM);
    cudaFuncSetAttribute(gemm_hmma_kernel<KT_PROJ>,
                         cudaFuncAttributeMaxDynamicSharedMemorySize, GEMM_SMEM);

    // 0) conversions
    round_kernel<<<(Mrows * Cdim / 4 + 255) / 256, 256>>>(x, xh, Mrows * Cdim / 4);
    build_bt_kernel<<<dim3(ThreeC / 32, Cdim / 32), dim3(32, 8)>>>(
        Wqkv, bqkv, ThreeC, 1536, 0);
    build_bt_kernel<<<dim3(Cdim / 32, Cdim / 32), dim3(32, 8)>>>(
        Wproj, bprojt, Cdim, 2304, 1);

    // 1) qkv = x @ Wqkv  (fp16 2-term: xh @ (Bh+Bl))
    gemm_hmma_kernel<KT_QKV><<<dim3(ThreeC / BN, Mrows / BM), 512, GEMM_SMEM>>>(
        xh, xh, bqkv, 1536, qkv_ptr, ThreeC, nullptr);

    // 2-3) fused context + exp-sum partials, then reduce
    ctx_partial_kernel<<<dim3(BH, NSPLIT), 256>>>();
    ctx_reduce_kernel<<<(BH * Dd * Dd + 255) / 256, 256>>>();

    // 4) attn = q @ ctx -> fp16 hi/lo
    attn_out_kernel<<<dim3(BH, Nseq / 128), 256>>>();

    // 5) out = attn @ Wproj + bias  (fp16 3-term)
    gemm_hmma_kernel<KT_PROJ><<<dim3(Cdim / BN, Mrows / BM), 512, GEMM_SMEM>>>(
        ah, al, bprojt, 2304, out, Cdim, bproj);
}

// round 13
// speedup vs baseline: 2.1258x; 1.5638x over previous
#include <cuda_runtime.h>
#include <cuda_fp16.h>
#include <cstdint>

// Problem constants
#define Bdim 8
#define Nseq 4096
#define Cdim 768
#define Hh   12
#define Dd   64
#define Mrows (Bdim * Nseq)      // 32768
#define ThreeC (3 * Cdim)        // 2304
#define BH (Bdim * Hh)           // 96
#define NSPLIT 16

// K-tile counts (32-wide):
#define KT_QKV  24               // K' = 768:  1-term  xh @ Bh
#define KT_PROJ 48               // K' = 1536: 2-term  ah @ [Bh;Bl]

// GEMM tiling (proven config)
#define BM 128
#define BN 256
#define BKK 32
#define ROWB 80                  // smem row stride bytes (64B data + 16B pad)
#define ATILE (BM * ROWB)
#define BTILE (BN * ROWB)
#define STG (ATILE + BTILE)      // 30720
#define NSTAGE 4
#define GEMM_SMEM (NSTAGE * STG) // 122880

// ---------------------------------------------------------------------------
// Scratch (device globals -- no allocation allowed)
// ---------------------------------------------------------------------------
__device__ float   g_qkv[(size_t)Mrows * ThreeC];     // 302 MB fp32
__device__ __half  g_xh[(size_t)Mrows * Cdim];        // x rounded to fp16
__device__ __half  g_ah[(size_t)Mrows * Cdim];        // attn rounded to fp16
__device__ __half  g_bqkv[(size_t)ThreeC * 768];      // Wqkv^T hi only
__device__ __half  g_bproj[(size_t)Cdim * 1536];      // Wproj^T [Bh|Bl]
__device__ float g_psum[NSPLIT * BH * Dd];
__device__ float g_ctxp[(size_t)NSPLIT * BH * Dd * Dd];
__device__ float g_ctx[BH * Dd * Dd];

// ---------------------------------------------------------------------------
// PTX helpers (arch-portable: cp.async + ldmatrix + mma.sync only)
// ---------------------------------------------------------------------------
__device__ __forceinline__ uint32_t smem_u32_of(const void* p) {
    uint32_t a;
    asm("{ .reg .u64 t; cvta.to.shared.u64 t, %1; cvt.u32.u64 %0, t; }"
        : "=r"(a) : "l"(p));
    return a;
}

__device__ __forceinline__ void cp_async16(uint32_t dst, const void* src) {
    asm volatile("cp.async.cg.shared.global [%0], [%1], 16;\n"
                 :: "r"(dst), "l"(src) : "memory");
}
#define CP_COMMIT() asm volatile("cp.async.commit_group;" ::: "memory")
#define CP_WAIT2()  asm volatile("cp.async.wait_group 2;" ::: "memory")
#define CP_WAIT1()  asm volatile("cp.async.wait_group 1;" ::: "memory")
#define CP_WAIT0()  asm volatile("cp.async.wait_group 0;" ::: "memory")

__device__ __forceinline__ void ldmatrix_x4(uint32_t* r, uint32_t addr) {
    asm volatile(
        "ldmatrix.sync.aligned.m8n8.x4.shared.b16 {%0,%1,%2,%3}, [%4];"
        : "=r"(r[0]), "=r"(r[1]), "=r"(r[2]), "=r"(r[3]) : "r"(addr));
}

__device__ __forceinline__ void mma16816(float* d, const uint32_t* a,
                                         const uint32_t* b) {
    asm volatile(
        "mma.sync.aligned.m16n8k16.row.col.f32.f16.f16.f32 "
        "{%0,%1,%2,%3}, {%4,%5,%6,%7}, {%8,%9}, {%0,%1,%2,%3};"
        : "+f"(d[0]), "+f"(d[1]), "+f"(d[2]), "+f"(d[3])
        : "r"(a[0]), "r"(a[1]), "r"(a[2]), "r"(a[3]), "r"(b[0]), "r"(b[1]));
}

__device__ __forceinline__ void split2h(float v, __half& h, __half& l) {
    h = __float2half(v);
    l = __float2half(v - __half2float(h));
}

// ---------------------------------------------------------------------------
// GEMM: C[M, Ntot] fp32 = fp16 A'' (M x 32*KTT) @ B''t (Ntot x 32*KTT)^T
// A columns wrap mod 768 (blocks of 24 kt). B'' rows laid out [Bh(|Bl)].
// BM=128 BN=256 BK=32, 512 threads (warp 4m x 4n), 4-stage cp.async.
// ---------------------------------------------------------------------------
__device__ __forceinline__ void gemm_load_stage(
    const __half* __restrict__ A,
    const __half* __restrict__ Bt, int ldb,
    size_t m0, size_t n0, int kt, int stage, uint32_t sb, int tid)
{
    int blk = kt / 24;
    int acol = (kt - blk * 24) * BKK;
    int bcol = kt * BKK;
    uint32_t as = sb + stage * STG;
    uint32_t bs = as + ATILE;
    int lr = tid >> 2;
    int lc = tid & 3;

    cp_async16(as + lr * ROWB + lc * 16,
               A + (m0 + lr) * Cdim + acol + lc * 8);
    cp_async16(bs + lr * ROWB + lc * 16,
               Bt + (n0 + lr) * (size_t)ldb + bcol + lc * 8);
    cp_async16(bs + (lr + 128) * ROWB + lc * 16,
               Bt + (n0 + lr + 128) * (size_t)ldb + bcol + lc * 8);
    CP_COMMIT();
}

template <int KTT>
__global__ __launch_bounds__(512, 1) void gemm_hmma_kernel(
    const __half* __restrict__ A,
    const __half* __restrict__ Bt, int ldb,
    float* __restrict__ Cm, int ldc,
    const float* __restrict__ bias)
{
    extern __shared__ char smem[];
    uint32_t sb = smem_u32_of(smem);
    int tid = threadIdx.x;
    int lane = tid & 31, wid = tid >> 5;
    int wm = wid >> 2, wn = wid & 3;

    size_t m0 = (size_t)blockIdx.y * BM;
    size_t n0 = (size_t)blockIdx.x * BN;

    uint32_t a_off = (uint32_t)(wm * 32 + (lane & 15)) * ROWB + ((lane >> 4) << 4);
    uint32_t b_off = ATILE +
        (uint32_t)(wn * 64 + (lane & 7) + ((lane >> 4) << 3)) * ROWB +
        ((lane & 8) << 1);

    float acc[2][8][4];
    #pragma unroll
    for (int mf = 0; mf < 2; mf++)
        #pragma unroll
        for (int nf = 0; nf < 8; nf++)
            #pragma unroll
            for (int c = 0; c < 4; c++) acc[mf][nf][c] = 0.f;

    gemm_load_stage(A, Bt, ldb, m0, n0, 0, 0, sb, tid);
    gemm_load_stage(A, Bt, ldb, m0, n0, 1, 1, sb, tid);
    gemm_load_stage(A, Bt, ldb, m0, n0, 2, 2, sb, tid);

    for (int kt = 0; kt < KTT; kt++) {
        int rem = KTT - 1 - kt;
        if (rem >= 2) CP_WAIT2();
        else if (rem == 1) CP_WAIT1();
        else CP_WAIT0();
        __syncthreads();
        if (kt + 3 < KTT)
            gemm_load_stage(A, Bt, ldb, m0, n0, kt + 3, (kt + 3) & 3, sb, tid);

        uint32_t stg = sb + (kt & 3) * STG;
        #pragma unroll
        for (int ks = 0; ks < 2; ks++) {
            uint32_t aF[2][4];
            uint32_t bF[4][4];
            #pragma unroll
            for (int mf = 0; mf < 2; mf++)
                ldmatrix_x4(aF[mf], stg + a_off + mf * (16 * ROWB) + ks * 32);
            #pragma unroll
            for (int nf2 = 0; nf2 < 4; nf2++)
                ldmatrix_x4(bF[nf2], stg + b_off + nf2 * (16 * ROWB) + ks * 32);
            #pragma unroll
            for (int mf = 0; mf < 2; mf++)
                #pragma unroll
                for (int nf = 0; nf < 8; nf++)
                    mma16816(acc[mf][nf], aF[mf], &bF[nf >> 1][(nf & 1) * 2]);
        }
    }

    #pragma unroll
    for (int mf = 0; mf < 2; mf++) {
        size_t row = m0 + wm * 32 + mf * 16 + (lane >> 2);
        #pragma unroll
        for (int nf = 0; nf < 8; nf++) {
            int col = (int)n0 + wn * 64 + nf * 8 + (lane & 3) * 2;
            float b0 = 0.f, b1 = 0.f;
            if (bias) { b0 = bias[col]; b1 = bias[col + 1]; }
            float2 v0; v0.x = acc[mf][nf][0] + b0; v0.y = acc[mf][nf][1] + b1;
            float2 v1; v1.x = acc[mf][nf][2] + b0; v1.y = acc[mf][nf][3] + b1;
            *reinterpret_cast<float2*>(&Cm[row * (size_t)ldc + col]) = v0;
            *reinterpret_cast<float2*>(&Cm[(row + 8) * (size_t)ldc + col]) = v1;
        }
    }
}

// ---------------------------------------------------------------------------
// Round x fp32 -> fp16
// ---------------------------------------------------------------------------
__global__ __launch_bounds__(256) void round_kernel(
    const float* __restrict__ in, __half* __restrict__ hi, int n4)
{
    int i = blockIdx.x * 256 + threadIdx.x;
    if (i >= n4) return;
    float4 v = reinterpret_cast<const float4*>(in)[i];
    __half2* hp = reinterpret_cast<__half2*>(hi) + i * 2;
    __half2 a; a.x = __float2half(v.x); a.y = __float2half(v.y);
    __half2 b; b.x = __float2half(v.z); b.y = __float2half(v.w);
    hp[0] = a; hp[1] = b;
}

// ---------------------------------------------------------------------------
// Build transposed weight: W [768 x Nn] fp32 -> Bt [Nn x ldb] fp16
// nterms==1: rows = [Bh];  nterms==2: rows = [Bh | Bl]
// ---------------------------------------------------------------------------
__global__ __launch_bounds__(256) void build_bt_kernel(
    const float* __restrict__ W, __half* __restrict__ Bt, int Nn,
    int ldb, int nterms)
{
    __shared__ float t[32][33];
    int n0 = blockIdx.x * 32, k0 = blockIdx.y * 32;
    int tx = threadIdx.x, ty = threadIdx.y;   // (32, 8)
    #pragma unroll
    for (int j = 0; j < 32; j += 8)
        t[ty + j][tx] = W[(size_t)(k0 + ty + j) * Nn + n0 + tx];
    __syncthreads();
    #pragma unroll
    for (int j = 0; j < 32; j += 8) {
        int n = n0 + ty + j, k = k0 + tx;
        float v = t[tx][ty + j];
        __half h, l;
        split2h(v, h, l);
        size_t base = (size_t)n * ldb;
        Bt[base + k] = h;
        if (nterms >= 2) Bt[base + 768 + k] = l;
    }
}

// ---------------------------------------------------------------------------
// Partial context + partial exp-sums (no max subtraction: k ~ N(0,1), safe).
// ---------------------------------------------------------------------------
__global__ __launch_bounds__(256) void ctx_partial_kernel()
{
    int bh = blockIdx.x, split = blockIdx.y;
    int b = bh / Hh, h = bh - b * Hh;
    int n_start = split * (Nseq / NSPLIT);

    const float* kbase = g_qkv + (size_t)b * Nseq * ThreeC + Cdim + h * Dd;
    const float* vbase = g_qkv + (size_t)b * Nseq * ThreeC + 2 * Cdim + h * Dd;

    __shared__ float ks[16][68];
    __shared__ float vs[16][68];

    int tid = threadIdx.x;
    int lr = tid >> 4, lc = (tid & 15) * 4;
    int rowd = (tid >> 4) * 4, cole = (tid & 15) * 4;

    float acc[4][4];
    #pragma unroll
    for (int i = 0; i < 4; i++)
        #pragma unroll
        for (int j = 0; j < 4; j++) acc[i][j] = 0.f;
    float sum4[4] = {0.f, 0.f, 0.f, 0.f};

    for (int nt = 0; nt < Nseq / NSPLIT; nt += 16) {
        size_t off = (size_t)(n_start + nt + lr) * ThreeC + lc;
        float4 kv = *reinterpret_cast<const float4*>(&kbase[off]);
        float e0 = __expf(kv.x), e1 = __expf(kv.y);
        float e2 = __expf(kv.z), e3 = __expf(kv.w);
        ks[lr][lc + 0] = e0; ks[lr][lc + 1] = e1;
        ks[lr][lc + 2] = e2; ks[lr][lc + 3] = e3;
        sum4[0] += e0; sum4[1] += e1; sum4[2] += e2; sum4[3] += e3;
        *reinterpret_cast<float4*>(&vs[lr][lc]) =
            *reinterpret_cast<const float4*>(&vbase[off]);
        __syncthreads();

        #pragma unroll
        for (int kk = 0; kk < 16; kk++) {
            float4 a = *reinterpret_cast<const float4*>(&ks[kk][rowd]);
            float4 bb = *reinterpret_cast<const float4*>(&vs[kk][cole]);
            float af[4] = {a.x, a.y, a.z, a.w};
            float bv[4] = {bb.x, bb.y, bb.z, bb.w};
            #pragma unroll
            for (int i = 0; i < 4; i++)
                #pragma unroll
                for (int j = 0; j < 4; j++)
                    acc[i][j] += af[i] * bv[j];
        }
        __syncthreads();
    }

    float* outp = g_ctxp + (size_t)(split * BH + bh) * (Dd * Dd);
    #pragma unroll
    for (int i = 0; i < 4; i++) {
        float4 o;
        o.x = acc[i][0]; o.y = acc[i][1]; o.z = acc[i][2]; o.w = acc[i][3];
        *reinterpret_cast<float4*>(&outp[(rowd + i) * Dd + cole]) = o;
    }

    ks[lr][lc + 0] = sum4[0]; ks[lr][lc + 1] = sum4[1];
    ks[lr][lc + 2] = sum4[2]; ks[lr][lc + 3] = sum4[3];
    __syncthreads();
    if (tid < 64) {
        float s = 0.f;
        #pragma unroll
        for (int r = 0; r < 16; r++) s += ks[r][tid];
        g_psum[(split * BH + bh) * Dd + tid] = s;
    }
}

__global__ __launch_bounds__(256) void ctx_reduce_kernel()
{
    int idx = blockIdx.x * 256 + threadIdx.x;
    const int total = BH * Dd * Dd;
    if (idx >= total) return;
    int bh = idx >> 12;
    int d = (idx & 4095) >> 6;
    float ksum = 0.f;
    float s = 0.f;
    #pragma unroll
    for (int sp = 0; sp < NSPLIT; sp++) {
        ksum += g_psum[(sp * BH + bh) * Dd + d];
        s += g_ctxp[(size_t)sp * total + idx];
    }
    g_ctx[idx] = s / ksum;
}

// ---------------------------------------------------------------------------
// attn = q @ ctx -> write fp16 (A-side of GEMM2, single term)
// ---------------------------------------------------------------------------
__global__ __launch_bounds__(256) void attn_out_kernel()
{
    int bh = blockIdx.x, nb = blockIdx.y;
    int b = bh / Hh, h = bh - b * Hh;
    int n0 = nb * 128;

    __shared__ float q_s[128][17];
    __shared__ float ctx_s[16][64];

    const float* qbase = g_qkv + (size_t)b * Nseq * ThreeC + h * Dd;
    const float* cbase = g_ctx + (size_t)bh * (Dd * Dd);

    int tid = threadIdx.x;
    int rowb = (tid >> 4) * 8;
    int col  = (tid & 15) * 4;

    float acc[8][4];
    #pragma unroll
    for (int i = 0; i < 8; i++)
        #pragma unroll
        for (int j = 0; j < 4; j++) acc[i][j] = 0.f;

    for (int dc = 0; dc < Dd; dc += 16) {
        #pragma unroll
        for (int t = 0; t < 2; t++) {
            int idx = tid + t * 256;
            int r = idx >> 2;
            int c4 = (idx & 3) * 4;
            float4 qv = *reinterpret_cast<const float4*>(
                &qbase[(size_t)(n0 + r) * ThreeC + dc + c4]);
            q_s[r][c4 + 0] = qv.x; q_s[r][c4 + 1] = qv.y;
            q_s[r][c4 + 2] = qv.z; q_s[r][c4 + 3] = qv.w;
        }
        {
            int r = tid >> 4;
            int c4 = (tid & 15) * 4;
            *reinterpret_cast<float4*>(&ctx_s[r][c4]) =
                *reinterpret_cast<const float4*>(&cbase[(size_t)(dc + r) * Dd + c4]);
        }
        __syncthreads();

        #pragma unroll
        for (int dd = 0; dd < 16; dd++) {
            float4 cf = *reinterpret_cast<const float4*>(&ctx_s[dd][col]);
            float cv[4] = {cf.x, cf.y, cf.z, cf.w};
            #pragma unroll
            for (int i = 0; i < 8; i++) {
                float qv = q_s[rowb + i][dd];
                #pragma unroll
                for (int j = 0; j < 4; j++) acc[i][j] += qv * cv[j];
            }
        }
        __syncthreads();
    }

    #pragma unroll
    for (int i = 0; i < 8; i++) {
        size_t base = ((size_t)b * Nseq + n0 + rowb + i) * Cdim + h * Dd + col;
        __half2* hp = reinterpret_cast<__half2*>(&g_ah[base]);
        __half2 p0; p0.x = __float2half(acc[i][0]); p0.y = __float2half(acc[i][1]);
        __half2 p1; p1.x = __float2half(acc[i][2]); p1.y = __float2half(acc[i][3]);
        hp[0] = p0; hp[1] = p1;
    }
}

// ---------------------------------------------------------------------------
extern "C" void kernel_launch(void* const* d_in, const int* in_sizes, int n_in,
                              void* d_out, int out_size)
{
    const float* x     = (const float*)d_in[0];   // [8,4096,768]
    const float* Wqkv  = (const float*)d_in[1];   // [768,2304]
    const float* Wproj = (const float*)d_in[2];   // [768,768]
    const float* bproj = (const float*)d_in[3];   // [768]
    float* out = (float*)d_out;

    float *qkv_ptr;
    __half *xh, *ah, *bqkv, *bprojt;
    cudaGetSymbolAddress((void**)&qkv_ptr, g_qkv);
    cudaGetSymbolAddress((void**)&xh, g_xh);
    cudaGetSymbolAddress((void**)&ah, g_ah);
    cudaGetSymbolAddress((void**)&bqkv, g_bqkv);
    cudaGetSymbolAddress((void**)&bprojt, g_bproj);

    cudaFuncSetAttribute(gemm_hmma_kernel<KT_QKV>,
                         cudaFuncAttributeMaxDynamicSharedMemorySize, GEMM_SMEM);
    cudaFuncSetAttribute(gemm_hmma_kernel<KT_PROJ>,
                         cudaFuncAttributeMaxDynamicSharedMemorySize, GEMM_SMEM);

    // 0) conversions
    round_kernel<<<(Mrows * Cdim / 4 + 255) / 256, 256>>>(x, xh, Mrows * Cdim / 4);
    build_bt_kernel<<<dim3(ThreeC / 32, Cdim / 32), dim3(32, 8)>>>(
        Wqkv, bqkv, ThreeC, 768, 1);
    build_bt_kernel<<<dim3(Cdim / 32, Cdim / 32), dim3(32, 8)>>>(
        Wproj, bprojt, Cdim, 1536, 2);

    // 1) qkv = xh @ Bh  (fp16 1-term)
    gemm_hmma_kernel<KT_QKV><<<dim3(ThreeC / BN, Mrows / BM), 512, GEMM_SMEM>>>(
        xh, bqkv, 768, qkv_ptr, ThreeC, nullptr);

    // 2-3) fused context + exp-sum partials, then reduce
    ctx_partial_kernel<<<dim3(BH, NSPLIT), 256>>>();
    ctx_reduce_kernel<<<(BH * Dd * Dd + 255) / 256, 256>>>();

    // 4) attn = q @ ctx -> fp16
    attn_out_kernel<<<dim3(BH, Nseq / 128), 256>>>();

    // 5) out = ah @ [Bh;Bl] + bias  (fp16 2-term)
    gemm_hmma_kernel<KT_PROJ><<<dim3(Cdim / BN, Mrows / BM), 512, GEMM_SMEM>>>(
        ah, bprojt, 1536, out, Cdim, bproj);
}